// round 1
// baseline (speedup 1.0000x reference)
#include <cuda_runtime.h>

// Locally-connected 2D: out[b,o,y,x] = sum_k patches[b,y,x,k] * W[y,x,o,k] + bias[y,x,o]
// x: [128, 3, 64, 64] f32
// W: [60, 60, 32, 75] f32  (k flatten order: c*25 + kh*5 + kw)
// b: [60, 60, 32] f32
// out: [128, 32, 60, 60] f32

#define RYX   60
#define BATCH 128
#define OC    32
#define KTOT  75   // 3 * 5 * 5

__global__ __launch_bounds__(256, 4)
void lc2d_kernel(const float* __restrict__ x,
                 const float* __restrict__ W,
                 const float* __restrict__ bias,
                 float* __restrict__ out)
{
    __shared__ float sW[KTOT * OC];     // [k][o]   (transposed from [o][k])
    __shared__ float sP[KTOT * BATCH];  // [k][b]
    __shared__ float sB[OC];

    const int pos = blockIdx.x;           // pos = y*60 + x  (x fastest -> adjacent CTAs share L2 lines on store)
    const int py  = pos / RYX;
    const int px  = pos % RYX;
    const int t   = threadIdx.x;

    // ---- load W[pos] transposed to [k][o] ----
    // idx enumerates (k, o) with o fastest: gmem reads stride-75 scatter (same 9.6KB region,
    // all lines consumed), smem writes fully coalesced / conflict-free.
    const float* Wp = W + (size_t)pos * (OC * KTOT);
    #pragma unroll 4
    for (int idx = t; idx < KTOT * OC; idx += 256) {
        int k = idx >> 5;          // idx / 32
        int o = idx & 31;
        sW[k * OC + o] = Wp[o * KTOT + k];
    }
    if (t < OC) sB[t] = bias[pos * OC + t];

    // ---- load 128 patches into [k][b] ----
    #pragma unroll 4
    for (int idx = t; idx < KTOT * BATCH; idx += 256) {
        int k  = idx >> 7;         // idx / 128
        int b  = idx & 127;
        int c  = k / 25;
        int r  = (k % 25) / 5;
        int cc = k % 5;
        sP[k * BATCH + b] =
            x[ (((size_t)b * 3 + c) * 64 + (py + r)) * 64 + (px + cc) ];
    }
    __syncthreads();

    // ---- register-tiled compute: 4 batches x 4 output channels per thread ----
    const int ot = t & 7;          // 8 o-tiles
    const int bt = t >> 3;         // 32 b-tiles
    const int o0 = ot * 4;
    const int b0 = bt * 4;

    float4 a0 = make_float4(0.f, 0.f, 0.f, 0.f);   // a[bi] spans 4 o's
    float4 a1 = a0, a2 = a0, a3 = a0;

    #pragma unroll 15
    for (int k = 0; k < KTOT; k++) {
        const float4 w = *reinterpret_cast<const float4*>(&sW[k * OC + o0]);
        const float4 p = *reinterpret_cast<const float4*>(&sP[k * BATCH + b0]);
        a0.x += p.x * w.x; a0.y += p.x * w.y; a0.z += p.x * w.z; a0.w += p.x * w.w;
        a1.x += p.y * w.x; a1.y += p.y * w.y; a1.z += p.y * w.z; a1.w += p.y * w.w;
        a2.x += p.z * w.x; a2.y += p.z * w.y; a2.z += p.z * w.z; a2.w += p.z * w.w;
        a3.x += p.w * w.x; a3.y += p.w * w.y; a3.z += p.w * w.z; a3.w += p.w * w.w;
    }

    const float4 bv = *reinterpret_cast<const float4*>(&sB[o0]);

    // ---- store: out[(b*32 + o)*3600 + pos] ----
    const size_t posoff = (size_t)py * RYX + px;
    float ar[4][4] = {
        {a0.x, a0.y, a0.z, a0.w},
        {a1.x, a1.y, a1.z, a1.w},
        {a2.x, a2.y, a2.z, a2.w},
        {a3.x, a3.y, a3.z, a3.w},
    };
    const float bvr[4] = {bv.x, bv.y, bv.z, bv.w};

    #pragma unroll
    for (int bi = 0; bi < 4; bi++) {
        const size_t brow = (size_t)(b0 + bi) * OC;
        #pragma unroll
        for (int oj = 0; oj < 4; oj++) {
            out[(brow + (o0 + oj)) * (RYX * RYX) + posoff] = ar[bi][oj] + bvr[oj];
        }
    }
}

extern "C" void kernel_launch(void* const* d_in, const int* in_sizes, int n_in,
                              void* d_out, int out_size)
{
    const float* x    = (const float*)d_in[0];  // [128,3,64,64]
    const float* W    = (const float*)d_in[1];  // [60,60,32,75]
    const float* bias = (const float*)d_in[2];  // [60,60,32]
    float* out        = (float*)d_out;          // [128,32,60,60]

    dim3 grid(RYX * RYX);   // 3600 positions
    dim3 block(256);
    lc2d_kernel<<<grid, block>>>(x, W, bias, out);
}

// round 2
// speedup vs baseline: 3.0321x; 3.0321x over previous
#include <cuda_runtime.h>
#include <cstdint>

// Locally-connected 2D:
//   out[b,o,y,x] = sum_k patches[b,y,x,k] * W[y,x,o,k] + bias[y,x,o]
// x: [128, 3, 64, 64] f32, W: [60,60,32,75] f32 (k = c*25 + kh*5 + kw),
// bias: [60,60,32] f32, out: [128,32,60,60] f32
//
// Plan:
//  1) pre-transpose x -> xT[c][h][w][b]  (b innermost, coalesced gathers later)
//  2) main kernel: CTA = (y, 4 consecutive x-positions). Stage x tile (b-major)
//     and W (raw o-major, bank-padded) in smem; packed fp32x2 FFMA2 compute;
//     px-fastest lane mapping so output stores coalesce.

#define RYX   60
#define BATCH 128
#define OC    32
#define KTOT  75
#define TX    4        // output positions per CTA
#define XCOLS 8        // TX + 5 - 1
#define NKK   120      // 3*5*XCOLS rows of x data
#define SXS   132      // sX row stride (bank spread: 4*kk + b)
#define SWR   77       // sW per-o row stride (13*o + k bank spread)
#define SWP   2466     // sW per-position stride (32*77 + 2 -> pl adds 2 mod 32)

typedef unsigned long long ull;

__device__ float g_xT[3 * 64 * 64 * 128];   // 6.29 MB scratch

// ---------------------------------------------------------------- transpose
__global__ __launch_bounds__(256)
void transpose_x_kernel(const float* __restrict__ x)
{
    __shared__ float tile[32][33];
    const int wt    = blockIdx.x & 1;    // w tile (2)
    const int btile = blockIdx.x >> 1;   // b tile (4)
    const int h     = blockIdx.y;        // 64
    const int c     = blockIdx.z;        // 3
    const int tx = threadIdx.x;          // 32
    const int ty = threadIdx.y;          // 8

    #pragma unroll
    for (int j = 0; j < 4; j++) {
        int b = btile * 32 + ty + j * 8;
        tile[ty + j * 8][tx] =
            x[(((size_t)b * 3 + c) * 64 + h) * 64 + wt * 32 + tx];
    }
    __syncthreads();
    #pragma unroll
    for (int j = 0; j < 4; j++) {
        int w = wt * 32 + ty + j * 8;
        g_xT[(((size_t)c * 64 + h) * 64 + w) * 128 + btile * 32 + tx] =
            tile[tx][ty + j * 8];
    }
}

// ---------------------------------------------------------------- main
__global__ __launch_bounds__(256, 2)
void lc2d_kernel(const float* __restrict__ W,
                 const float* __restrict__ bias,
                 float* __restrict__ out)
{
    extern __shared__ float smem[];
    float* sX = smem;                    // NKK * SXS  = 15840 floats
    float* sW = sX + NKK * SXS;          // TX * SWP   =  9864 floats
    float* sB = sW + TX * SWP;           // TX * OC    =   128 floats

    const int py   = blockIdx.x / 15;
    const int xt   = blockIdx.x % 15;
    const int px0  = xt * TX;
    const int pos0 = py * RYX + px0;
    const int t    = threadIdx.x;

    // ---- W: contiguous 9600-float coalesced read, padded o-major smem ----
    const float* Wg = W + (size_t)pos0 * (OC * KTOT);
    #pragma unroll 4
    for (int i = t; i < TX * OC * KTOT; i += 256) {
        int row = i / KTOT;                 // pl*32 + o
        int k   = i - row * KTOT;
        sW[(row >> 5) * SWP + (row & 31) * SWR + k] = Wg[i];
    }
    if (t < TX * OC) sB[t] = bias[pos0 * OC + t];

    // ---- x tile from xT: fully coalesced float4 both sides ----
    #pragma unroll 4
    for (int i = t; i < NKK * 32; i += 256) {      // 3840 float4 lanes
        int bq   = i & 31;
        int comb = i >> 5;                          // (c*5+r)*8 + col
        int c    = comb / 40;
        int rem  = comb - c * 40;
        int r    = rem >> 3;
        int col  = rem & 7;
        float4 v = *reinterpret_cast<const float4*>(
            &g_xT[(((size_t)c * 64 + py + r) * 64 + px0 + col) * 128 + bq * 4]);
        *reinterpret_cast<float4*>(&sX[comb * SXS + bq * 4]) = v;
    }
    __syncthreads();

    // ---- compute: thread = (pl fastest, ot, bt); tile 8o x 8b, f32x2 ----
    const int pl = t & 3;
    const int ot = (t >> 2) & 3;
    const int bt = t >> 4;            // 0..15
    const int o0 = ot * 8;
    const int b0 = bt * 8;

    const float* wp = sW + pl * SWP + o0 * SWR;   // + oi*SWR + k
    const float* xp = sX + pl * SXS + b0;         // + (cr*8+cc)*SXS

    ull acc[32];
    #pragma unroll
    for (int i = 0; i < 32; i++) acc[i] = 0ull;

    #pragma unroll
    for (int cr = 0; cr < 15; cr++) {            // c*5 + r
        #pragma unroll
        for (int cc = 0; cc < 5; cc++) {
            const float* xr = xp + (cr * 8 + cc) * SXS;
            ulonglong2 q0 = *reinterpret_cast<const ulonglong2*>(xr);
            ulonglong2 q1 = *reinterpret_cast<const ulonglong2*>(xr + 4);
            const int k = cr * 5 + cc;
            #pragma unroll
            for (int oi = 0; oi < 8; oi++) {
                unsigned wu = __float_as_uint(wp[oi * SWR + k]);
                ull wd;
                asm("mov.b64 %0, {%1, %1};" : "=l"(wd) : "r"(wu));
                asm("fma.rn.f32x2 %0, %1, %2, %0;" : "+l"(acc[oi*4+0]) : "l"(wd), "l"(q0.x));
                asm("fma.rn.f32x2 %0, %1, %2, %0;" : "+l"(acc[oi*4+1]) : "l"(wd), "l"(q0.y));
                asm("fma.rn.f32x2 %0, %1, %2, %0;" : "+l"(acc[oi*4+2]) : "l"(wd), "l"(q1.x));
                asm("fma.rn.f32x2 %0, %1, %2, %0;" : "+l"(acc[oi*4+3]) : "l"(wd), "l"(q1.y));
            }
        }
    }

    // ---- store: lanes pl-fastest -> 4 px merge into one 16B chunk ----
    const int posidx = pos0 + pl;
    #pragma unroll
    for (int oi = 0; oi < 8; oi++) {
        const float bv = sB[pl * OC + o0 + oi];
        #pragma unroll
        for (int bp = 0; bp < 4; bp++) {
            unsigned lo, hi;
            asm("mov.b64 {%0, %1}, %2;" : "=r"(lo), "=r"(hi) : "l"(acc[oi*4+bp]));
            const int b = b0 + bp * 2;
            const size_t base = ((size_t)b * OC + o0 + oi) * (RYX * RYX) + posidx;
            out[base]                      = __uint_as_float(lo) + bv;
            out[base + (size_t)OC * RYX * RYX] = __uint_as_float(hi) + bv;
        }
    }
}

// ---------------------------------------------------------------- launch
extern "C" void kernel_launch(void* const* d_in, const int* in_sizes, int n_in,
                              void* d_out, int out_size)
{
    const float* x    = (const float*)d_in[0];
    const float* W    = (const float*)d_in[1];
    const float* bias = (const float*)d_in[2];
    float* out        = (float*)d_out;

    static const int SMEM_BYTES = (NKK * SXS + TX * SWP + TX * OC) * 4; // 103328
    cudaFuncSetAttribute(lc2d_kernel,
                         cudaFuncAttributeMaxDynamicSharedMemorySize, SMEM_BYTES);

    transpose_x_kernel<<<dim3(8, 64, 3), dim3(32, 8)>>>(x);
    lc2d_kernel<<<dim3(RYX * 15), 256, SMEM_BYTES>>>(W, bias, out);
}